// round 13
// baseline (speedup 1.0000x reference)
#include <cuda_runtime.h>
#include <cuda.h>
#include <cuda_bf16.h>
#include <cstdint>

#define BSZ 8192
#define DIM 512
#define TM 128
#define TN 128
#define NTI (BSZ / TM)      // 64
#define NTJ (BSZ / TN)      // 64
#define NTILES (NTI * NTJ)  // 4096
#define NSTAGE 3
#define STA 16384           // A stage: 128 rows x 128 B
#define STB 16384           // B stage: 128 rows x 128 B
#define STAGE_BYTES (STA + STB)
#define SMEM_BYTES (1024 + NSTAGE * STAGE_BYTES)   // 99328
#define NWARP 8
#define TEMP_INV 2.0f
#define LOG2E 1.4426950408889634f
#define LOSS_EPS 1e-5f

// ---------------- scratch (device globals; allocation is forbidden) ----------------
__device__ __align__(1024) signed char g_Q8[BSZ * DIM];
__device__ __align__(1024) signed char g_K8[BSZ * DIM];
__device__ float g_Sq[BSZ];
__device__ float g_Sk[BSZ];
__device__ float g_diag[BSZ];
__device__ float g_Row[BSZ];
__device__ float g_Col[BSZ];

#define SWZ(x) ((x) ^ (((x) >> 3) & 0x70))

static __device__ __forceinline__ uint32_t smem_u32(const void* p) {
    uint32_t a;
    asm("{ .reg .u64 t; cvta.to.shared.u64 t, %1; cvt.u32.u64 %0, t; }"
        : "=r"(a) : "l"(p));
    return a;
}

static __device__ __forceinline__ float ex2(float x) {
    float r;
    asm("ex2.approx.ftz.f32 %0, %1;" : "=f"(r) : "f"(x));
    return r;
}

static __device__ __forceinline__ void ldm_x4(uint32_t* r, uint32_t addr) {
    asm volatile("ldmatrix.sync.aligned.m8n8.x4.shared.b16 {%0,%1,%2,%3}, [%4];"
                 : "=r"(r[0]), "=r"(r[1]), "=r"(r[2]), "=r"(r[3]) : "r"(addr));
}

static __device__ __forceinline__ void mma_s8(int* c, const uint32_t* a, const uint32_t* b) {
    asm volatile(
        "mma.sync.aligned.m16n8k32.row.col.s32.s8.s8.s32 "
        "{%0,%1,%2,%3}, {%4,%5,%6,%7}, {%8,%9}, {%0,%1,%2,%3};"
        : "+r"(c[0]), "+r"(c[1]), "+r"(c[2]), "+r"(c[3])
        : "r"(a[0]), "r"(a[1]), "r"(a[2]), "r"(a[3]), "r"(b[0]), "r"(b[1]));
}

static __device__ __forceinline__ void mbar_init(uint32_t mbar, uint32_t cnt) {
    asm volatile("mbarrier.init.shared.b64 [%0], %1;" :: "r"(mbar), "r"(cnt) : "memory");
}
static __device__ __forceinline__ void mbar_expect_tx(uint32_t mbar, uint32_t bytes) {
    asm volatile("mbarrier.arrive.expect_tx.shared.b64 _, [%0], %1;"
                 :: "r"(mbar), "r"(bytes) : "memory");
}
static __device__ __forceinline__ void mbar_wait(uint32_t mbar, uint32_t parity) {
    uint32_t done;
    asm volatile(
        "{\n\t.reg .pred p;\n\t"
        "mbarrier.try_wait.parity.acquire.cta.shared::cta.b64 p, [%1], %2;\n\t"
        "selp.b32 %0, 1, 0, p;\n\t}"
        : "=r"(done) : "r"(mbar), "r"(parity) : "memory");
    if (!done) {
        asm volatile(
            "{\n\t.reg .pred P1;\n\t"
            "W_LOOP_%=:\n\t"
            "mbarrier.try_wait.parity.acquire.cta.shared::cta.b64 P1, [%0], %1, 0x989680;\n\t"
            "@P1 bra.uni W_DONE_%=;\n\t"
            "bra.uni W_LOOP_%=;\n\t"
            "W_DONE_%=:\n\t}"
            :: "r"(mbar), "r"(parity) : "memory");
    }
}
static __device__ __forceinline__ void tma_2d(uint32_t saddr, const CUtensorMap* tmap,
                                              int x, int y, uint32_t mbar) {
    asm volatile(
        "cp.async.bulk.tensor.2d.shared::cta.global.tile.mbarrier::complete_tx::bytes "
        "[%0], [%1, {%2, %3}], [%4];"
        :: "r"(saddr), "l"(tmap), "r"(x), "r"(y), "r"(mbar) : "memory");
}

// ---------------- kernel 0: warp-per-row normalize + int8 quantize ----------------
static __device__ __forceinline__ float wsum(float v) {
    #pragma unroll
    for (int o = 16; o; o >>= 1) v += __shfl_xor_sync(0xffffffffu, v, o);
    return v;
}
static __device__ __forceinline__ float wmax(float v) {
    #pragma unroll
    for (int o = 16; o; o >>= 1) v = fmaxf(v, __shfl_xor_sync(0xffffffffu, v, o));
    return v;
}

__global__ void __launch_bounds__(256) k_norm(const float* __restrict__ q,
                                              const float* __restrict__ k,
                                              float* __restrict__ out) {
    const int lane = threadIdx.x & 31;
    const int row = blockIdx.x * 8 + (threadIdx.x >> 5);
    const float4* qr = (const float4*)(q + (size_t)row * DIM);
    const float4* kr = (const float4*)(k + (size_t)row * DIM);

    float a[16], b[16];
    #pragma unroll
    for (int i = 0; i < 4; i++) {
        float4 v = qr[lane + 32 * i];
        a[4 * i] = v.x; a[4 * i + 1] = v.y; a[4 * i + 2] = v.z; a[4 * i + 3] = v.w;
        float4 w = kr[lane + 32 * i];
        b[4 * i] = w.x; b[4 * i + 1] = w.y; b[4 * i + 2] = w.z; b[4 * i + 3] = w.w;
    }

    float sq = 0.f, sk = 0.f;
    #pragma unroll
    for (int i = 0; i < 16; i++) { sq += a[i] * a[i]; sk += b[i] * b[i]; }
    sq = wsum(sq); sk = wsum(sk);
    const float iq = 1.0f / fmaxf(sqrtf(sq), 1e-12f);
    const float ik = 1.0f / fmaxf(sqrtf(sk), 1e-12f);

    float dot = 0.f, mq = 0.f, mk = 0.f;
    #pragma unroll
    for (int i = 0; i < 16; i++) {
        a[i] *= iq; b[i] *= ik;
        dot += a[i] * b[i];
        mq = fmaxf(mq, fabsf(a[i]));
        mk = fmaxf(mk, fabsf(b[i]));
    }
    dot = wsum(dot);
    mq = fmaxf(wmax(mq), 1e-20f);
    mk = fmaxf(wmax(mk), 1e-20f);

    const float qa = 127.0f / mq, qb = 127.0f / mk;
    #pragma unroll
    for (int i = 0; i < 4; i++) {
        char4 ca, cb;
        ca.x = (char)__float2int_rn(a[4 * i] * qa);
        ca.y = (char)__float2int_rn(a[4 * i + 1] * qa);
        ca.z = (char)__float2int_rn(a[4 * i + 2] * qa);
        ca.w = (char)__float2int_rn(a[4 * i + 3] * qa);
        cb.x = (char)__float2int_rn(b[4 * i] * qb);
        cb.y = (char)__float2int_rn(b[4 * i + 1] * qb);
        cb.z = (char)__float2int_rn(b[4 * i + 2] * qb);
        cb.w = (char)__float2int_rn(b[4 * i + 3] * qb);
        ((char4*)g_Q8)[(size_t)row * 128 + lane + 32 * i] = ca;
        ((char4*)g_K8)[(size_t)row * 128 + lane + 32 * i] = cb;
    }

    if (lane == 0) {
        g_Sq[row] = mq * (1.0f / 127.0f);
        g_Sk[row] = mk * (1.0f / 127.0f);
        g_diag[row] = dot;
        g_Row[row] = 0.f;
        g_Col[row] = 0.f;
        if (row == 0) out[0] = 0.f;
    }
}

// ---------------- kernel 1: persistent IMMA, 2 CTAs/SM, mod-3 TMA ring ----------------
__global__ void __launch_bounds__(256, 2) k_gemm(const __grid_constant__ CUtensorMap tmapA,
                                                const __grid_constant__ CUtensorMap tmapB) {
    extern __shared__ __align__(1024) char smem[];
    const uint32_t sbase = smem_u32(smem);
    int* const cnt = (int*)(smem + 64);          // 3 stage counters
    const int tid = threadIdx.x, wid = tid >> 5, lane = tid & 31;
    const int warp_m = wid & 3;                  // 4 warps over M (32 rows each)
    const int warp_n = wid >> 2;                 // 2 warps over N (64 cols each)
    const int bid = blockIdx.x, G = gridDim.x;
    const int ntiles = (NTILES - 1 - bid) / G + 1;
    const int gtot = ntiles * 4;

    if (tid == 0) {
        #pragma unroll
        for (int s = 0; s < NSTAGE; s++) {
            mbar_init(sbase + s * 16, 1);        // full (tx-based)
            cnt[s] = 0;
        }
    }
    __syncthreads();

    auto produce = [&](int gp) {
        const int t = bid + (gp >> 2) * G;       // tile index (4 chunks per tile)
        const int s = gp % NSTAGE;               // stage index (mod-3 ring)
        const uint32_t stA = sbase + 1024 + s * STAGE_BYTES;
        const uint32_t fullb = sbase + s * 16;
        mbar_expect_tx(fullb, STAGE_BYTES);
        tma_2d(stA, &tmapA, (gp & 3) * 128, (t >> 6) * TM, fullb);
        tma_2d(stA + STA, &tmapB, (gp & 3) * 128, (t & 63) * TN, fullb);
    };

    if (tid == 0) {
        #pragma unroll
        for (int gp = 0; gp < NSTAGE; gp++) produce(gp);   // gtot >= 3 always
    }

    // ldmatrix geometry (verified byte mapping; warp tile 32x64)
    const int lg = lane >> 3;
    const int a_row = warp_m * 32 + (lane & 7) + ((lg & 1) << 3);
    const int a_kb = (lg >> 1) << 4;
    const int b_row = warp_n * 64 + (lane & 7) + ((lg >> 1) << 3);
    const int b_kb = (lg & 1) << 4;
    const int g8 = lane >> 2, qq = lane & 3;

    int g = 0;
    #pragma unroll 1
    for (int il = 0; il < ntiles; il++) {
        const int t = bid + il * G;
        const int ti = t >> 6, tj = t & 63;

        int acc[2][8][4];
        #pragma unroll
        for (int mi = 0; mi < 2; mi++)
            #pragma unroll
            for (int ni = 0; ni < 8; ni++)
                #pragma unroll
                for (int e = 0; e < 4; e++) acc[mi][ni][e] = 0;

        #pragma unroll 1
        for (int c = 0; c < 4; c++) {
            const int s = g % NSTAGE;
            const int phase = g / NSTAGE;
            const uint32_t fullb = sbase + s * 16;
            mbar_wait(fullb, phase & 1);
            const uint32_t sA = sbase + 1024 + s * STAGE_BYTES;
            const uint32_t sB = sA + STA;

            #pragma unroll
            for (int ks = 0; ks < 4; ks++) {
                const int kb = ks * 32;
                uint32_t a[2][4];
                #pragma unroll
                for (int mi = 0; mi < 2; mi++)
                    ldm_x4(a[mi], sA + SWZ((a_row + mi * 16) * 128 + kb + a_kb));
                #pragma unroll
                for (int np = 0; np < 4; np++) {
                    uint32_t b[4];
                    ldm_x4(b, sB + SWZ((b_row + np * 16) * 128 + kb + b_kb));
                    #pragma unroll
                    for (int mi = 0; mi < 2; mi++) {
                        mma_s8(acc[mi][np * 2 + 0], a[mi], b + 0);
                        mma_s8(acc[mi][np * 2 + 1], a[mi], b + 2);
                    }
                }
            }

            // this warp's reads of stage s retired (mma consumed them);
            // the 8th warp to bump the counter refills the stage — nobody waits.
            __syncwarp();
            if (lane == 0) {
                const int old = atomicAdd(&cnt[s], 1);
                if (old == (phase * NWARP + (NWARP - 1)) && g + NSTAGE < gtot)
                    produce(g + NSTAGE);
            }
            g++;
        }

        // ---- epilogue: dequant + exp2 + row/col sums (f32, R11-proven) ----
        float rA[2][2], rB[8][2];
        #pragma unroll
        for (int mi = 0; mi < 2; mi++) {
            const int r0 = ti * TM + warp_m * 32 + mi * 16 + g8;
            rA[mi][0] = g_Sq[r0] * (TEMP_INV * LOG2E);
            rA[mi][1] = g_Sq[r0 + 8] * (TEMP_INV * LOG2E);
        }
        #pragma unroll
        for (int ni = 0; ni < 8; ni++) {
            const int c0 = tj * TN + warp_n * 64 + ni * 8 + qq * 2;
            rB[ni][0] = g_Sk[c0];
            rB[ni][1] = g_Sk[c0 + 1];
        }

        float rs0[2] = {0.f, 0.f}, rs8[2] = {0.f, 0.f};
        float cs[8][2];
        #pragma unroll
        for (int ni = 0; ni < 8; ni++) cs[ni][0] = cs[ni][1] = 0.f;

        #pragma unroll
        for (int mi = 0; mi < 2; mi++)
            #pragma unroll
            for (int ni = 0; ni < 8; ni++) {
                float e0 = ex2((float)acc[mi][ni][0] * (rA[mi][0] * rB[ni][0]));
                float e1 = ex2((float)acc[mi][ni][1] * (rA[mi][0] * rB[ni][1]));
                float e2 = ex2((float)acc[mi][ni][2] * (rA[mi][1] * rB[ni][0]));
                float e3 = ex2((float)acc[mi][ni][3] * (rA[mi][1] * rB[ni][1]));
                rs0[mi] += e0 + e1;
                rs8[mi] += e2 + e3;
                cs[ni][0] += e0 + e2;
                cs[ni][1] += e1 + e3;
            }

        #pragma unroll
        for (int mi = 0; mi < 2; mi++) {
            rs0[mi] += __shfl_xor_sync(0xffffffffu, rs0[mi], 1);
            rs0[mi] += __shfl_xor_sync(0xffffffffu, rs0[mi], 2);
            rs8[mi] += __shfl_xor_sync(0xffffffffu, rs8[mi], 1);
            rs8[mi] += __shfl_xor_sync(0xffffffffu, rs8[mi], 2);
        }
        if ((lane & 3) == 0) {
            const int rbase = ti * TM + warp_m * 32 + g8;
            #pragma unroll
            for (int mi = 0; mi < 2; mi++) {
                atomicAdd(&g_Row[rbase + mi * 16], rs0[mi]);
                atomicAdd(&g_Row[rbase + mi * 16 + 8], rs8[mi]);
            }
        }

        #pragma unroll
        for (int ni = 0; ni < 8; ni++)
            #pragma unroll
            for (int j = 0; j < 2; j++) {
                cs[ni][j] += __shfl_xor_sync(0xffffffffu, cs[ni][j], 4);
                cs[ni][j] += __shfl_xor_sync(0xffffffffu, cs[ni][j], 8);
                cs[ni][j] += __shfl_xor_sync(0xffffffffu, cs[ni][j], 16);
            }
        if (lane < 4) {
            const int cbase = tj * TN + warp_n * 64 + lane * 2;
            #pragma unroll
            for (int ni = 0; ni < 8; ni++) {
                atomicAdd(&g_Col[cbase + ni * 8], cs[ni][0]);
                atomicAdd(&g_Col[cbase + ni * 8 + 1], cs[ni][1]);
            }
        }
    }
}

// ---------------- kernel 2: final loss ----------------
__global__ void __launch_bounds__(128) k_loss(float* __restrict__ out) {
    __shared__ float sb[4];
    const int i = blockIdx.x * 128 + threadIdx.x;
    const float rs = g_Row[i], cs = g_Col[i], d = g_diag[i];
    const float ep = __expf(d * TEMP_INV);
    float term = -logf(ep / rs + LOSS_EPS) - logf(ep / cs + LOSS_EPS);
    #pragma unroll
    for (int o = 16; o; o >>= 1) term += __shfl_xor_sync(0xffffffffu, term, o);
    __syncthreads();
    if ((threadIdx.x & 31) == 0) sb[threadIdx.x >> 5] = term;
    __syncthreads();
    if (threadIdx.x == 0)
        atomicAdd(out, ((sb[0] + sb[1]) + (sb[2] + sb[3])) * (1.0f / (float)BSZ));
}

// ---------------- launch ----------------
typedef CUresult (*PFN_encodeTiled)(CUtensorMap*, CUtensorMapDataType, cuuint32_t, void*,
                                    const cuuint64_t*, const cuuint64_t*, const cuuint32_t*,
                                    const cuuint32_t*, CUtensorMapInterleave, CUtensorMapSwizzle,
                                    CUtensorMapL2promotion, CUtensorMapFloatOOBfill);

extern "C" void kernel_launch(void* const* d_in, const int* in_sizes, int n_in,
                              void* d_out, int out_size) {
    (void)in_sizes; (void)n_in; (void)out_size;
    const float* q = (const float*)d_in[0];
    const float* k = (const float*)d_in[1];
    float* out = (float*)d_out;

    void* fn = nullptr;
    cudaDriverEntryPointQueryResult st;
    cudaGetDriverEntryPoint("cuTensorMapEncodeTiled", &fn, cudaEnableDefault, &st);
    PFN_encodeTiled encode = (PFN_encodeTiled)fn;

    void *pQ = nullptr, *pK = nullptr;
    cudaGetSymbolAddress(&pQ, g_Q8);
    cudaGetSymbolAddress(&pK, g_K8);

    cuuint64_t dims[2] = {DIM, BSZ};
    cuuint64_t strides[1] = {DIM};
    cuuint32_t boxA[2] = {128, TM};
    cuuint32_t boxB[2] = {128, TN};
    cuuint32_t es[2] = {1, 1};

    CUtensorMap tA, tB;
    encode(&tA, CU_TENSOR_MAP_DATA_TYPE_UINT8, 2, pQ, dims, strides, boxA, es,
           CU_TENSOR_MAP_INTERLEAVE_NONE, CU_TENSOR_MAP_SWIZZLE_128B,
           CU_TENSOR_MAP_L2_PROMOTION_L2_128B, CU_TENSOR_MAP_FLOAT_OOB_FILL_NONE);
    encode(&tB, CU_TENSOR_MAP_DATA_TYPE_UINT8, 2, pK, dims, strides, boxB, es,
           CU_TENSOR_MAP_INTERLEAVE_NONE, CU_TENSOR_MAP_SWIZZLE_128B,
           CU_TENSOR_MAP_L2_PROMOTION_L2_128B, CU_TENSOR_MAP_FLOAT_OOB_FILL_NONE);

    int nsm = 148;
    cudaDeviceGetAttribute(&nsm, cudaDevAttrMultiProcessorCount, 0);

    cudaFuncSetAttribute(k_gemm, cudaFuncAttributeMaxDynamicSharedMemorySize, SMEM_BYTES);

    k_norm<<<BSZ / 8, 256>>>(q, k, out);
    k_gemm<<<2 * nsm, 256, SMEM_BYTES>>>(tA, tB);
    k_loss<<<BSZ / 128, 128>>>(out);
}

// round 14
// speedup vs baseline: 1.0506x; 1.0506x over previous
#include <cuda_runtime.h>
#include <cuda.h>
#include <cuda_bf16.h>
#include <cstdint>

#define BSZ 8192
#define DIM 512
#define TM 128
#define TN 256
#define NTI (BSZ / TM)      // 64
#define NTJ (BSZ / TN)      // 32
#define NTILES (NTI * NTJ)  // 2048
#define NSTAGE 4
#define STA 16384           // A stage: 128 rows x 128 B
#define STB 32768           // B stage: 256 rows x 128 B
#define STAGE_BYTES (STA + STB)
#define SMEM_BYTES (1024 + NSTAGE * STAGE_BYTES)
#define NWARP 16
#define TEMP_INV 2.0f
#define LOG2E 1.4426950408889634f
#define LOSS_EPS 1e-5f

// ---------------- scratch (device globals; allocation is forbidden) ----------------
__device__ __align__(1024) signed char g_Q8[BSZ * DIM];
__device__ __align__(1024) signed char g_K8[BSZ * DIM];
__device__ float g_Sq[BSZ];
__device__ float g_Sk[BSZ];
__device__ float g_diag[BSZ];
__device__ float g_Row[BSZ];
__device__ float g_Col[BSZ];

#define SWZ(x) ((x) ^ (((x) >> 3) & 0x70))

static __device__ __forceinline__ uint32_t smem_u32(const void* p) {
    uint32_t a;
    asm("{ .reg .u64 t; cvta.to.shared.u64 t, %1; cvt.u32.u64 %0, t; }"
        : "=r"(a) : "l"(p));
    return a;
}

static __device__ __forceinline__ float ex2(float x) {
    float r;
    asm("ex2.approx.ftz.f32 %0, %1;" : "=f"(r) : "f"(x));
    return r;
}

static __device__ __forceinline__ void ldm_x4(uint32_t* r, uint32_t addr) {
    asm volatile("ldmatrix.sync.aligned.m8n8.x4.shared.b16 {%0,%1,%2,%3}, [%4];"
                 : "=r"(r[0]), "=r"(r[1]), "=r"(r[2]), "=r"(r[3]) : "r"(addr));
}

static __device__ __forceinline__ void mma_s8(int* c, const uint32_t* a, const uint32_t* b) {
    asm volatile(
        "mma.sync.aligned.m16n8k32.row.col.s32.s8.s8.s32 "
        "{%0,%1,%2,%3}, {%4,%5,%6,%7}, {%8,%9}, {%0,%1,%2,%3};"
        : "+r"(c[0]), "+r"(c[1]), "+r"(c[2]), "+r"(c[3])
        : "r"(a[0]), "r"(a[1]), "r"(a[2]), "r"(a[3]), "r"(b[0]), "r"(b[1]));
}

static __device__ __forceinline__ void mbar_init(uint32_t mbar, uint32_t cnt) {
    asm volatile("mbarrier.init.shared.b64 [%0], %1;" :: "r"(mbar), "r"(cnt) : "memory");
}
static __device__ __forceinline__ void mbar_expect_tx(uint32_t mbar, uint32_t bytes) {
    asm volatile("mbarrier.arrive.expect_tx.shared.b64 _, [%0], %1;"
                 :: "r"(mbar), "r"(bytes) : "memory");
}
static __device__ __forceinline__ void mbar_wait(uint32_t mbar, uint32_t parity) {
    uint32_t done;
    asm volatile(
        "{\n\t.reg .pred p;\n\t"
        "mbarrier.try_wait.parity.acquire.cta.shared::cta.b64 p, [%1], %2;\n\t"
        "selp.b32 %0, 1, 0, p;\n\t}"
        : "=r"(done) : "r"(mbar), "r"(parity) : "memory");
    if (!done) {
        asm volatile(
            "{\n\t.reg .pred P1;\n\t"
            "W_LOOP_%=:\n\t"
            "mbarrier.try_wait.parity.acquire.cta.shared::cta.b64 P1, [%0], %1, 0x989680;\n\t"
            "@P1 bra.uni W_DONE_%=;\n\t"
            "bra.uni W_LOOP_%=;\n\t"
            "W_DONE_%=:\n\t}"
            :: "r"(mbar), "r"(parity) : "memory");
    }
}
static __device__ __forceinline__ void tma_2d(uint32_t saddr, const CUtensorMap* tmap,
                                              int x, int y, uint32_t mbar) {
    asm volatile(
        "cp.async.bulk.tensor.2d.shared::cta.global.tile.mbarrier::complete_tx::bytes "
        "[%0], [%1, {%2, %3}], [%4];"
        :: "r"(saddr), "l"(tmap), "r"(x), "r"(y), "r"(mbar) : "memory");
}

// ---------------- kernel 0: two-pass warp-per-row normalize + int8 quantize ----------------
static __device__ __forceinline__ float wsum(float v) {
    #pragma unroll
    for (int o = 16; o; o >>= 1) v += __shfl_xor_sync(0xffffffffu, v, o);
    return v;
}
static __device__ __forceinline__ float wmax(float v) {
    #pragma unroll
    for (int o = 16; o; o >>= 1) v = fmaxf(v, __shfl_xor_sync(0xffffffffu, v, o));
    return v;
}

__global__ void __launch_bounds__(256) k_norm(const float* __restrict__ q,
                                              const float* __restrict__ k,
                                              float* __restrict__ out) {
    const int lane = threadIdx.x & 31;
    const int row = blockIdx.x * 8 + (threadIdx.x >> 5);
    const float4* qr = (const float4*)(q + (size_t)row * DIM);
    const float4* kr = (const float4*)(k + (size_t)row * DIM);

    // pass 1: stream both rows once; 5 scalar accumulators, transient regs only
    float sq = 0.f, sk = 0.f, sqk = 0.f, mqr = 0.f, mkr = 0.f;
    #pragma unroll
    for (int i = 0; i < 4; i++) {
        const float4 v = qr[lane + 32 * i];
        const float4 w = kr[lane + 32 * i];
        sq += v.x * v.x + v.y * v.y + v.z * v.z + v.w * v.w;
        sk += w.x * w.x + w.y * w.y + w.z * w.z + w.w * w.w;
        sqk += v.x * w.x + v.y * w.y + v.z * w.z + v.w * w.w;
        mqr = fmaxf(mqr, fmaxf(fmaxf(fabsf(v.x), fabsf(v.y)), fmaxf(fabsf(v.z), fabsf(v.w))));
        mkr = fmaxf(mkr, fmaxf(fmaxf(fabsf(w.x), fabsf(w.y)), fmaxf(fabsf(w.z), fabsf(w.w))));
    }
    sq = wsum(sq); sk = wsum(sk); sqk = wsum(sqk);
    mqr = fmaxf(wmax(mqr), 1e-20f);
    mkr = fmaxf(wmax(mkr), 1e-20f);

    const float iq = 1.0f / fmaxf(sqrtf(sq), 1e-12f);
    const float ik = 1.0f / fmaxf(sqrtf(sk), 1e-12f);

    // quantized code = round(q_i * 127 / max|q|)  — iq cancels exactly
    const float qa = 127.0f / mqr, qb = 127.0f / mkr;

    // pass 2: reload (L1-hot), quantize, store
    #pragma unroll
    for (int i = 0; i < 4; i++) {
        const float4 v = qr[lane + 32 * i];
        const float4 w = kr[lane + 32 * i];
        char4 ca, cb;
        ca.x = (char)__float2int_rn(v.x * qa);
        ca.y = (char)__float2int_rn(v.y * qa);
        ca.z = (char)__float2int_rn(v.z * qa);
        ca.w = (char)__float2int_rn(v.w * qa);
        cb.x = (char)__float2int_rn(w.x * qb);
        cb.y = (char)__float2int_rn(w.y * qb);
        cb.z = (char)__float2int_rn(w.z * qb);
        cb.w = (char)__float2int_rn(w.w * qb);
        ((char4*)g_Q8)[(size_t)row * 128 + lane + 32 * i] = ca;
        ((char4*)g_K8)[(size_t)row * 128 + lane + 32 * i] = cb;
    }

    if (lane == 0) {
        g_Sq[row] = mqr * iq * (1.0f / 127.0f);
        g_Sk[row] = mkr * ik * (1.0f / 127.0f);
        g_diag[row] = sqk * iq * ik;
        g_Row[row] = 0.f;
        g_Col[row] = 0.f;
        if (row == 0) out[0] = 0.f;
    }
}

// ---------------- kernel 1: persistent IMMA, 16 warps, last-arriver-produces ring ----------------
// (byte-identical to the 98.3 us round-11 build)
__global__ void __launch_bounds__(512, 1) k_gemm(const __grid_constant__ CUtensorMap tmapA,
                                                const __grid_constant__ CUtensorMap tmapB) {
    extern __shared__ __align__(1024) char smem[];
    const uint32_t sbase = smem_u32(smem);
    int* const cnt = (int*)(smem + 64);          // 4 stage counters
    const int tid = threadIdx.x, wid = tid >> 5, lane = tid & 31;
    const int warp_m = wid & 3;                  // 4 warps over M (32 rows each)
    const int warp_n = wid >> 2;                 // 4 warps over N (64 cols each)
    const int bid = blockIdx.x, G = gridDim.x;
    const int ntiles = (NTILES - 1 - bid) / G + 1;
    const int gtot = ntiles * 4;

    if (tid == 0) {
        #pragma unroll
        for (int s = 0; s < NSTAGE; s++) {
            mbar_init(sbase + s * 16, 1);        // full (tx-based)
            cnt[s] = 0;
        }
    }
    __syncthreads();

    auto produce = [&](int gp) {
        const int t = bid + (gp >> 2) * G;
        const int s = gp & 3;
        const uint32_t stA = sbase + 1024 + s * STAGE_BYTES;
        const uint32_t fullb = sbase + s * 16;
        mbar_expect_tx(fullb, STAGE_BYTES);
        tma_2d(stA, &tmapA, s * 128, (t >> 5) * TM, fullb);
        tma_2d(stA + STA, &tmapB, s * 128, (t & 31) * TN, fullb);
    };

    if (tid == 0) {
        #pragma unroll
        for (int gp = 0; gp < NSTAGE; gp++) produce(gp);   // gtot >= 4 always
    }

    // ldmatrix geometry (verified byte mapping; warp tile 32x64)
    const int lg = lane >> 3;
    const int a_row = warp_m * 32 + (lane & 7) + ((lg & 1) << 3);
    const int a_kb = (lg >> 1) << 4;
    const int b_row = warp_n * 64 + (lane & 7) + ((lg >> 1) << 3);
    const int b_kb = (lg & 1) << 4;
    const int g8 = lane >> 2, qq = lane & 3;

    int g = 0;
    #pragma unroll 1
    for (int il = 0; il < ntiles; il++) {
        const int t = bid + il * G;
        const int ti = t >> 5, tj = t & 31;

        int acc[2][8][4];
        #pragma unroll
        for (int mi = 0; mi < 2; mi++)
            #pragma unroll
            for (int ni = 0; ni < 8; ni++)
                #pragma unroll
                for (int e = 0; e < 4; e++) acc[mi][ni][e] = 0;

        #pragma unroll 1
        for (int c = 0; c < 4; c++) {
            const int s = g & 3;
            const uint32_t fullb = sbase + s * 16;
            mbar_wait(fullb, (g >> 2) & 1);
            const uint32_t sA = sbase + 1024 + s * STAGE_BYTES;
            const uint32_t sB = sA + STA;

            #pragma unroll
            for (int ks = 0; ks < 4; ks++) {
                const int kb = ks * 32;
                uint32_t a[2][4];
                #pragma unroll
                for (int mi = 0; mi < 2; mi++)
                    ldm_x4(a[mi], sA + SWZ((a_row + mi * 16) * 128 + kb + a_kb));
                #pragma unroll
                for (int np = 0; np < 4; np++) {
                    uint32_t b[4];
                    ldm_x4(b, sB + SWZ((b_row + np * 16) * 128 + kb + b_kb));
                    #pragma unroll
                    for (int mi = 0; mi < 2; mi++) {
                        mma_s8(acc[mi][np * 2 + 0], a[mi], b + 0);
                        mma_s8(acc[mi][np * 2 + 1], a[mi], b + 2);
                    }
                }
            }

            // all this warp's reads of stage s retired (mma consumed them);
            // the 16th warp to bump the counter refills the stage — nobody waits.
            __syncwarp();
            if (lane == 0) {
                const int old = atomicAdd(&cnt[s], 1);
                if (old == ((g >> 2) * NWARP + (NWARP - 1)) && g + NSTAGE < gtot)
                    produce(g + NSTAGE);
            }
            g++;
        }

        // ---- epilogue: dequant + exp2 + row/col sums ----
        float rA[2][2], rB[8][2];
        #pragma unroll
        for (int mi = 0; mi < 2; mi++) {
            const int r0 = ti * TM + warp_m * 32 + mi * 16 + g8;
            rA[mi][0] = g_Sq[r0] * (TEMP_INV * LOG2E);
            rA[mi][1] = g_Sq[r0 + 8] * (TEMP_INV * LOG2E);
        }
        #pragma unroll
        for (int ni = 0; ni < 8; ni++) {
            const int c0 = tj * TN + warp_n * 64 + ni * 8 + qq * 2;
            rB[ni][0] = g_Sk[c0];
            rB[ni][1] = g_Sk[c0 + 1];
        }

        float rs0[2] = {0.f, 0.f}, rs8[2] = {0.f, 0.f};
        float cs[8][2];
        #pragma unroll
        for (int ni = 0; ni < 8; ni++) cs[ni][0] = cs[ni][1] = 0.f;

        #pragma unroll
        for (int mi = 0; mi < 2; mi++)
            #pragma unroll
            for (int ni = 0; ni < 8; ni++) {
                float e0 = ex2((float)acc[mi][ni][0] * (rA[mi][0] * rB[ni][0]));
                float e1 = ex2((float)acc[mi][ni][1] * (rA[mi][0] * rB[ni][1]));
                float e2 = ex2((float)acc[mi][ni][2] * (rA[mi][1] * rB[ni][0]));
                float e3 = ex2((float)acc[mi][ni][3] * (rA[mi][1] * rB[ni][1]));
                rs0[mi] += e0 + e1;
                rs8[mi] += e2 + e3;
                cs[ni][0] += e0 + e2;
                cs[ni][1] += e1 + e3;
            }

        #pragma unroll
        for (int mi = 0; mi < 2; mi++) {
            rs0[mi] += __shfl_xor_sync(0xffffffffu, rs0[mi], 1);
            rs0[mi] += __shfl_xor_sync(0xffffffffu, rs0[mi], 2);
            rs8[mi] += __shfl_xor_sync(0xffffffffu, rs8[mi], 1);
            rs8[mi] += __shfl_xor_sync(0xffffffffu, rs8[mi], 2);
        }
        if ((lane & 3) == 0) {
            const int rbase = ti * TM + warp_m * 32 + g8;
            #pragma unroll
            for (int mi = 0; mi < 2; mi++) {
                atomicAdd(&g_Row[rbase + mi * 16], rs0[mi]);
                atomicAdd(&g_Row[rbase + mi * 16 + 8], rs8[mi]);
            }
        }

        #pragma unroll
        for (int ni = 0; ni < 8; ni++)
            #pragma unroll
            for (int j = 0; j < 2; j++) {
                cs[ni][j] += __shfl_xor_sync(0xffffffffu, cs[ni][j], 4);
                cs[ni][j] += __shfl_xor_sync(0xffffffffu, cs[ni][j], 8);
                cs[ni][j] += __shfl_xor_sync(0xffffffffu, cs[ni][j], 16);
            }
        if (lane < 4) {
            const int cbase = tj * TN + warp_n * 64 + lane * 2;
            #pragma unroll
            for (int ni = 0; ni < 8; ni++) {
                atomicAdd(&g_Col[cbase + ni * 8], cs[ni][0]);
                atomicAdd(&g_Col[cbase + ni * 8 + 1], cs[ni][1]);
            }
        }
    }
}

// ---------------- kernel 2: final loss ----------------
__global__ void __launch_bounds__(128) k_loss(float* __restrict__ out) {
    __shared__ float sb[4];
    const int i = blockIdx.x * 128 + threadIdx.x;
    const float rs = g_Row[i], cs = g_Col[i], d = g_diag[i];
    const float ep = __expf(d * TEMP_INV);
    float term = -logf(ep / rs + LOSS_EPS) - logf(ep / cs + LOSS_EPS);
    #pragma unroll
    for (int o = 16; o; o >>= 1) term += __shfl_xor_sync(0xffffffffu, term, o);
    __syncthreads();
    if ((threadIdx.x & 31) == 0) sb[threadIdx.x >> 5] = term;
    __syncthreads();
    if (threadIdx.x == 0)
        atomicAdd(out, ((sb[0] + sb[1]) + (sb[2] + sb[3])) * (1.0f / (float)BSZ));
}

// ---------------- launch ----------------
typedef CUresult (*PFN_encodeTiled)(CUtensorMap*, CUtensorMapDataType, cuuint32_t, void*,
                                    const cuuint64_t*, const cuuint64_t*, const cuuint32_t*,
                                    const cuuint32_t*, CUtensorMapInterleave, CUtensorMapSwizzle,
                                    CUtensorMapL2promotion, CUtensorMapFloatOOBfill);

extern "C" void kernel_launch(void* const* d_in, const int* in_sizes, int n_in,
                              void* d_out, int out_size) {
    (void)in_sizes; (void)n_in; (void)out_size;
    const float* q = (const float*)d_in[0];
    const float* k = (const float*)d_in[1];
    float* out = (float*)d_out;

    void* fn = nullptr;
    cudaDriverEntryPointQueryResult st;
    cudaGetDriverEntryPoint("cuTensorMapEncodeTiled", &fn, cudaEnableDefault, &st);
    PFN_encodeTiled encode = (PFN_encodeTiled)fn;

    void *pQ = nullptr, *pK = nullptr;
    cudaGetSymbolAddress(&pQ, g_Q8);
    cudaGetSymbolAddress(&pK, g_K8);

    cuuint64_t dims[2] = {DIM, BSZ};
    cuuint64_t strides[1] = {DIM};
    cuuint32_t boxA[2] = {128, TM};
    cuuint32_t boxB[2] = {128, TN};
    cuuint32_t es[2] = {1, 1};

    CUtensorMap tA, tB;
    encode(&tA, CU_TENSOR_MAP_DATA_TYPE_UINT8, 2, pQ, dims, strides, boxA, es,
           CU_TENSOR_MAP_INTERLEAVE_NONE, CU_TENSOR_MAP_SWIZZLE_128B,
           CU_TENSOR_MAP_L2_PROMOTION_L2_128B, CU_TENSOR_MAP_FLOAT_OOB_FILL_NONE);
    encode(&tB, CU_TENSOR_MAP_DATA_TYPE_UINT8, 2, pK, dims, strides, boxB, es,
           CU_TENSOR_MAP_INTERLEAVE_NONE, CU_TENSOR_MAP_SWIZZLE_128B,
           CU_TENSOR_MAP_L2_PROMOTION_L2_128B, CU_TENSOR_MAP_FLOAT_OOB_FILL_NONE);

    int nsm = 148;
    cudaDeviceGetAttribute(&nsm, cudaDevAttrMultiProcessorCount, 0);

    cudaFuncSetAttribute(k_gemm, cudaFuncAttributeMaxDynamicSharedMemorySize, SMEM_BYTES);

    k_norm<<<BSZ / 8, 256>>>(q, k, out);
    k_gemm<<<nsm, 512, SMEM_BYTES>>>(tA, tB);
    k_loss<<<BSZ / 128, 128>>>(out);
}